// round 3
// baseline (speedup 1.0000x reference)
#include <cuda_runtime.h>
#include <math.h>

typedef unsigned long long ull;

// ---------------------------------------------------------------------------
// Packed f32x2 helpers (sm_103a FFMA2 path)
// ---------------------------------------------------------------------------
__device__ __forceinline__ void upk2(ull v, float& lo, float& hi) {
    asm("mov.b64 {%0, %1}, %2;" : "=f"(lo), "=f"(hi) : "l"(v));
}
__device__ __forceinline__ void fma2(ull& d, ull a, ull b) {
    asm("fma.rn.f32x2 %0, %1, %2, %0;" : "+l"(d) : "l"(a), "l"(b));
}
__device__ __forceinline__ ull lds64(const float* p) {
    return *reinterpret_cast<const ull*>(p);
}

// ---------------------------------------------------------------------------
// Intermediate activation buffers (device globals — no allocation allowed).
// Layouts all [B, C, T, D, H, W] contiguous.
// ---------------------------------------------------------------------------
__device__ float g_a1[38880000];   // 256*3*15^4
__device__ float g_a2[15925248];   // 256*3*12^4
__device__ float g_a3[6718464];    // 256*4*9^4
__device__ float g_a4[1658880];    // 256*5*6^4

__host__ __device__ constexpr int slice_pitch(int s3) { return (s3 + 6) & ~1; }

// ---------------------------------------------------------------------------
// Row engine v3: all activation pairs come from two SMEM copies —
//   c0[i] = slice[i], c1[i] = slice[i+1]
// so pair{slice[q],slice[q+1]} = aligned LDS.64 (c0+q if q even, c1+q-1 if odd).
// Weights are pre-duplicated float2{w,w} -> broadcast LDS.64. No packing movs.
// w2 points at the (ci,kt,kd,kh) block; co stride = COS float2s, kw stride 1.
// ---------------------------------------------------------------------------
template<int CO, int K, int RP, int COS, bool EVENP>
__device__ __forceinline__ void row_v3(const float* __restrict__ c0,
                                       const float* __restrict__ c1,
                                       int p,
                                       const float2* __restrict__ w2,
                                       ull (&acc)[CO][RP])
{
    const float *pe, *po;
    if (EVENP) { pe = c0 + p; po = c1 + p; }
    else {
        const bool odd = p & 1;
        pe = odd ? (c1 + p - 1) : (c0 + p);
        po = odd ? (c0 + p + 1) : (c1 + p);
    }
    constexpr int ME = RP + (K > 2 ? 1 : 0);   // pairs for even kw taps
    constexpr int MO = RP + (K > 3 ? 1 : 0);   // pairs for odd kw taps

    {   // even taps: kw = 0, 2, ...
        ull E[ME];
#pragma unroll
        for (int m = 0; m < ME; m++) E[m] = lds64(pe + 2 * m);
#pragma unroll
        for (int kw = 0; kw < K; kw += 2)
#pragma unroll
            for (int co = 0; co < CO; co++) {
                const ull wv = lds64(reinterpret_cast<const float*>(w2 + co * COS + kw));
#pragma unroll
                for (int j = 0; j < RP; j++)
                    fma2(acc[co][j], E[(kw >> 1) + j], wv);
            }
    }
    {   // odd taps: kw = 1, 3, ...
        ull Od[MO];
#pragma unroll
        for (int m = 0; m < MO; m++) Od[m] = lds64(po + 2 * m);
#pragma unroll
        for (int kw = 1; kw < K; kw += 2)
#pragma unroll
            for (int co = 0; co < CO; co++) {
                const ull wv = lds64(reinterpret_cast<const float*>(w2 + co * COS + kw));
#pragma unroll
                for (int j = 0; j < RP; j++)
                    fma2(acc[co][j], Od[((kw - 1) >> 1) + j], wv);
            }
    }
}

// ---------------------------------------------------------------------------
// convA: rolling t-slice conv (+bias+ReLU). Block = (b, t-chunk).
// Thread = (t_local, d, h) computes the full W row for all COUT.
// SMEM: slice copies c0/c1 (single-buffered) + duplicated weights (float2).
// ---------------------------------------------------------------------------
template<int CIN, int COUT, int K, int S, int TLOC, int NTHR>
__global__ void __launch_bounds__(NTHR)
convA(const float* __restrict__ in, float* __restrict__ out,
      const float* __restrict__ w, const float* __restrict__ bias)
{
    constexpr int O = S - K + 1, TCH = O / TLOC, NST = TLOC + K - 1;
    constexpr int S2 = S * S, S3 = S2 * S, S4 = S3 * S;
    constexpr int O2 = O * O, O3 = O2 * O;
    constexpr int K4 = K * K * K * K, NW = COUT * CIN * K4, NACT = TLOC * O2;
    constexpr int RP = (O + 1) / 2;
    constexpr int SLP = slice_pitch(S3);
    constexpr bool EVENP = (S % 2) == 0;

    extern __shared__ float dsm[];            // c0[SLP] + c1[SLP]
    float* c0 = dsm;
    float* c1 = dsm + SLP;
    __shared__ float2 s_w2[NW];

    const int bt = blockIdx.x, tch = bt % TCH, b = bt / TCH;
    const int t0 = tch * TLOC, tid = threadIdx.x;

    for (int i = tid; i < NW; i += NTHR) {
        const float v = w[i];
        s_w2[i] = make_float2(v, v);
    }

    const int tl = tid / O2, rem = tid - tl * O2, dd = rem / O, hh = rem - dd * O;
    const bool act = tid < NACT;

    ull acc[COUT][RP];
#pragma unroll
    for (int c = 0; c < COUT; c++)
#pragma unroll
        for (int j = 0; j < RP; j++) acc[c][j] = 0ull;

    constexpr int NSL = CIN * NST;
#pragma unroll 1
    for (int idx = 0; idx < NSL; idx++) {
        const int ci = idx / NST, s = idx - ci * NST;
        __syncthreads();
        {
            const float* src = in + ((size_t)b * CIN + ci) * S4 + (size_t)(t0 + s) * S3;
            for (int i = tid; i < S3; i += NTHR) {
                const float v = src[i];
                c0[i] = v;
                if (i > 0) c1[i - 1] = v;
            }
        }
        __syncthreads();

        const int kt = s - tl;
        if (act && kt >= 0 && kt < K) {
#pragma unroll 1
            for (int kd = 0; kd < K; kd++) {
#pragma unroll 1
                for (int kh = 0; kh < K; kh++) {
                    const int p = (dd + kd) * S2 + (hh + kh) * S;
                    const float2* wq = s_w2 + (((ci * K + kt) * K + kd) * K + kh) * K;
                    row_v3<COUT, K, RP, CIN * K4, EVENP>(c0, c1, p, wq, acc);
                }
            }
        }
    }

    if (act) {
        const int t = t0 + tl;
#pragma unroll
        for (int co = 0; co < COUT; co++) {
            const float bv = bias[co];
            float* op = out + ((size_t)b * COUT + co) * ((size_t)O * O3)
                            + (size_t)t * O3 + (dd * O + hh) * O;
#pragma unroll
            for (int j = 0; j < RP; j++) {
                float v0, v1; upk2(acc[co][j], v0, v1);
                op[2 * j] = fmaxf(v0 + bv, 0.0f);
                if (2 * j + 1 < O) op[2 * j + 1] = fmaxf(v1 + bv, 0.0f);
            }
        }
    }
}

// ---------------------------------------------------------------------------
// convB: whole-volume conv (L5) + fused FC1/ReLU/FC2/sigmoid head.
// Block = b; thread = (t,d,h). Stages one input channel volume at a time.
// ---------------------------------------------------------------------------
template<int CIN, int COUT, int K, int S, int NTHR>
__global__ void __launch_bounds__(NTHR)
convB_fc(const float* __restrict__ in, float* __restrict__ out,
         const float* __restrict__ w, const float* __restrict__ bias,
         const float* __restrict__ fc1w, const float* __restrict__ fc1b,
         const float* __restrict__ fc2w, const float* __restrict__ fc2b)
{
    constexpr int O = S - K + 1;
    constexpr int S2 = S * S, S3 = S2 * S, S4 = S3 * S;
    constexpr int O2 = O * O, O3 = O2 * O, O4 = O * O3;
    constexpr int K4 = K * K * K * K, NW = COUT * CIN * K4;
    constexpr int NACT = O * O2;
    constexpr int RP = (O + 1) / 2;
    constexpr int VP = slice_pitch(S4);
    constexpr bool EVENP = (S % 2) == 0;
    constexpr int NF = COUT * O4;             // 1280

    extern __shared__ float dsm[];            // c0[VP] + c1[VP]
    float* c0 = dsm;
    float* c1 = dsm + VP;
    __shared__ float2 s_w2[NW];
    __shared__ float  s_h[NF];
    __shared__ float  s_so[33];

    const int b = blockIdx.x, tid = threadIdx.x;
    for (int i = tid; i < NW; i += NTHR) {
        const float v = w[i];
        s_w2[i] = make_float2(v, v);
    }

    const int tl = tid / O2, rem = tid - tl * O2, dd = rem / O, hh = rem - dd * O;
    const bool act = tid < NACT;

    ull acc[COUT][RP];
#pragma unroll
    for (int c = 0; c < COUT; c++)
#pragma unroll
        for (int j = 0; j < RP; j++) acc[c][j] = 0ull;

#pragma unroll 1
    for (int ci = 0; ci < CIN; ci++) {
        __syncthreads();
        {
            const float* src = in + ((size_t)b * CIN + ci) * S4;
            for (int i = tid; i < S4; i += NTHR) {
                const float v = src[i];
                c0[i] = v;
                if (i > 0) c1[i - 1] = v;
            }
        }
        __syncthreads();
        if (act) {
#pragma unroll 1
            for (int kt = 0; kt < K; kt++) {
#pragma unroll 1
                for (int kd = 0; kd < K; kd++) {
#pragma unroll 1
                    for (int kh = 0; kh < K; kh++) {
                        const int p = (tl + kt) * S3 + (dd + kd) * S2 + (hh + kh) * S;
                        const float2* wq = s_w2 + (((ci * K + kt) * K + kd) * K + kh) * K;
                        row_v3<COUT, K, RP, CIN * K4, EVENP>(c0, c1, p, wq, acc);
                    }
                }
            }
        }
    }

    // conv output -> SMEM flat [co][t][d][h][w] with bias+ReLU
    if (act) {
#pragma unroll
        for (int co = 0; co < COUT; co++) {
            const float bv = bias[co];
            float* op = s_h + co * O4 + tl * O3 + (dd * O + hh) * O;
#pragma unroll
            for (int j = 0; j < RP; j++) {
                float v0, v1; upk2(acc[co][j], v0, v1);
                op[2 * j] = fmaxf(v0 + bv, 0.0f);
                if (2 * j + 1 < O) op[2 * j + 1] = fmaxf(v1 + bv, 0.0f);
            }
        }
    }
    __syncthreads();

    if (tid < 33) {
        const float* wr = fc1w + tid * NF;
        float a0 = 0.f, a1 = 0.f, a2 = 0.f, a3 = 0.f;
#pragma unroll 4
        for (int k = 0; k < NF; k += 4) {
            a0 = fmaf(s_h[k + 0], __ldg(wr + k + 0), a0);
            a1 = fmaf(s_h[k + 1], __ldg(wr + k + 1), a1);
            a2 = fmaf(s_h[k + 2], __ldg(wr + k + 2), a2);
            a3 = fmaf(s_h[k + 3], __ldg(wr + k + 3), a3);
        }
        s_so[tid] = fmaxf((a0 + a1) + (a2 + a3) + fc1b[tid], 0.0f);
    }
    __syncthreads();
    if (tid == 0) {
        float z = fc2b[0];
#pragma unroll
        for (int j = 0; j < 33; j++) z = fmaf(s_so[j], __ldg(fc2w + j), z);
        out[b] = 1.0f / (1.0f + expf(-z));
    }
}

// ---------------------------------------------------------------------------
// Inputs (metadata order):
// 0:x 1:w1 2:b1 3:w2 4:b2 5:w3 6:b3 7:w4 8:b4 9:w5 10:b5
// 11:fc1_w 12:fc1_b 13:fc2_w 14:fc2_b    -> out: [B,1] float32
// ---------------------------------------------------------------------------
extern "C" void kernel_launch(void* const* d_in, const int* in_sizes, int n_in,
                              void* d_out, int out_size)
{
    const float* x   = (const float*)d_in[0];
    const float* w1  = (const float*)d_in[1];
    const float* b1  = (const float*)d_in[2];
    const float* w2  = (const float*)d_in[3];
    const float* b2  = (const float*)d_in[4];
    const float* w3  = (const float*)d_in[5];
    const float* b3  = (const float*)d_in[6];
    const float* w4  = (const float*)d_in[7];
    const float* b4  = (const float*)d_in[8];
    const float* w5  = (const float*)d_in[9];
    const float* b5  = (const float*)d_in[10];
    const float* f1w = (const float*)d_in[11];
    const float* f1b = (const float*)d_in[12];
    const float* f2w = (const float*)d_in[13];
    const float* f2b = (const float*)d_in[14];

    const int B = in_sizes[0] / (18 * 18 * 18 * 18);

    float *a1, *a2, *a3, *a4;
    cudaGetSymbolAddress((void**)&a1, g_a1);
    cudaGetSymbolAddress((void**)&a2, g_a2);
    cudaGetSymbolAddress((void**)&a3, g_a3);
    cudaGetSymbolAddress((void**)&a4, g_a4);

    constexpr int SM1 = 2 * slice_pitch(18 * 18 * 18) * 4;       // ~46.7 KB
    constexpr int SM2 = 2 * slice_pitch(15 * 15 * 15) * 4;       // ~27.0 KB
    constexpr int SM3 = 2 * slice_pitch(12 * 12 * 12) * 4;       // ~13.9 KB
    constexpr int SM4 = 2 * slice_pitch(9 * 9 * 9) * 4;          //  ~5.9 KB
    constexpr int SM5 = 2 * slice_pitch(6 * 6 * 6 * 6) * 4;      // ~10.4 KB

    cudaFuncSetAttribute(convA<1, 3, 4, 18, 1, 256>,
                         cudaFuncAttributeMaxDynamicSharedMemorySize, SM1);
    cudaFuncSetAttribute(convA<3, 3, 4, 15, 2, 288>,
                         cudaFuncAttributeMaxDynamicSharedMemorySize, SM2);
    cudaFuncSetAttribute(convA<3, 4, 4, 12, 3, 256>,
                         cudaFuncAttributeMaxDynamicSharedMemorySize, SM3);
    cudaFuncSetAttribute(convA<4, 5, 4, 9, 3, 128>,
                         cudaFuncAttributeMaxDynamicSharedMemorySize, SM4);
    cudaFuncSetAttribute(convB_fc<5, 5, 3, 6, 128>,
                         cudaFuncAttributeMaxDynamicSharedMemorySize, SM5);

    // L1: 18^4 -> 15^4, 1->3, k=4   (grid 3840, 225/256 active)
    convA<1, 3, 4, 18, 1, 256><<<B * 15, 256, SM1>>>(x,  a1, w1, b1);
    // L2: 15^4 -> 12^4, 3->3, k=4   (TLOC=2, grid 1536, 288/288 active)
    convA<3, 3, 4, 15, 2, 288><<<B * 6, 288, SM2>>>(a1, a2, w2, b2);
    // L3: 12^4 -> 9^4, 3->4, k=4    (TLOC=3, grid 768, 243/256 active)
    convA<3, 4, 4, 12, 3, 256><<<B * 3, 256, SM3>>>(a2, a3, w3, b3);
    // L4: 9^4 -> 6^4, 4->5, k=4     (TLOC=3, grid 512, 108/128 active)
    convA<4, 5, 4, 9, 3, 128><<<B * 2, 128, SM4>>>(a3, a4, w4, b4);
    // L5: 6^4 -> 4^4, 5->5, k=3 + fused FC1/ReLU/FC2/sigmoid -> d_out [B,1]
    convB_fc<5, 5, 3, 6, 128><<<B, 128, SM5>>>(a4, (float*)d_out, w5, b5,
                                               f1w, f1b, f2w, f2b);
}